// round 10
// baseline (speedup 1.0000x reference)
#include <cuda_runtime.h>
#include <cuda_fp16.h>
#include <cstdint>

#define BATCH      16
#define TSEQ       8192
#define MDIM       256
#define ROWS_TOTAL (BATCH * TSEQ)          // 131072
#define TILE_M     64
#define N_TILES    (ROWS_TOTAL / TILE_M)   // 2048
#define TILES_PER_B (TSEQ / TILE_M)        // 128
#define A_ROW_BYTES 528                    // 264 halves (256 + 8 pad)
#define A_BYTES    (TILE_M * A_ROW_BYTES)  // 33792
#define B_ROW_BYTES 144                    // 72 halves (64 + 8 pad)
#define B_BYTES    (MDIM * B_ROW_BYTES)    // 36864
#define DYN_SMEM   (1024 + A_BYTES + 2 * B_BYTES)   // 108544 (x2 CTA = 217KB/SM)

// ---------------- helpers ----------------
__device__ __forceinline__ uint32_t smem_u32(const void* p) {
    uint32_t a;
    asm("{ .reg .u64 t; cvta.to.shared.u64 t, %1; cvt.u32.u64 %0, t; }" : "=r"(a) : "l"(p));
    return a;
}
#define CP_ASYNC16(dst, src) \
    asm volatile("cp.async.cg.shared.global [%0], [%1], 16;" :: "r"(dst), "l"(src) : "memory")
#define CP_COMMIT() asm volatile("cp.async.commit_group;" ::: "memory")
#define CP_WAIT1()  asm volatile("cp.async.wait_group 1;" ::: "memory")
#define CP_WAIT0()  asm volatile("cp.async.wait_group 0;" ::: "memory")

__device__ __forceinline__ uint32_t lds_u32(uint32_t a) {
    uint32_t v;
    asm volatile("ld.shared.u32 %0, [%1];" : "=r"(v) : "r"(a));
    return v;
}
__device__ __forceinline__ void sts_u64(uint32_t a, uint32_t v0, uint32_t v1) {
    asm volatile("st.shared.v2.u32 [%0], {%1, %2};" :: "r"(a), "r"(v0), "r"(v1) : "memory");
}
__device__ __forceinline__ void mma16816(float* c, const uint32_t* a, uint32_t b0, uint32_t b1) {
    asm volatile(
        "mma.sync.aligned.m16n8k16.row.col.f32.f16.f16.f32 "
        "{%0,%1,%2,%3}, {%4,%5,%6,%7}, {%8,%9}, {%0,%1,%2,%3};"
        : "+f"(c[0]), "+f"(c[1]), "+f"(c[2]), "+f"(c[3])
        : "r"(a[0]), "r"(a[1]), "r"(a[2]), "r"(a[3]), "r"(b0), "r"(b1));
}
__device__ __forceinline__ float tanh_fast(float x) {
    float y;
    asm("tanh.approx.f32 %0, %1;" : "=f"(y) : "f"(x));
    return y;
}

// ---------------- global scratch ----------------
__device__ float  ap_cbias[MDIM];                 // vm @ W2
__device__ __half ap_Wt16[MDIM * MDIM];           // [n][k] = fp16(W1^T)
__device__ float  ap_partials[N_TILES * MDIM];    // per-CTA  sum_t e_t * x[t][col]
__device__ float  ap_sume[N_TILES];               // per-CTA  sum_t e_t

// ---------------- kernel 1a: W1^T -> fp16 ----------------
__global__ void __launch_bounds__(256) ap_prep_w_kernel(const float* __restrict__ W1) {
    const int b = blockIdx.x;          // k-range [b*8, b*8+8)
    const int n = threadIdx.x;
    __half h[8];
    #pragma unroll
    for (int j = 0; j < 8; j++)
        h[j] = __float2half_rn(W1[(b * 8 + j) * MDIM + n]);   // W1[k][n]
    *reinterpret_cast<uint4*>(ap_Wt16 + n * MDIM + b * 8) = *reinterpret_cast<uint4*>(h);
}

// ---------------- kernel 1b: cbias = vm @ W2 ----------------
__global__ void __launch_bounds__(1024) ap_prep_cbias_kernel(const float* __restrict__ W2,
                                                             const float* __restrict__ vm) {
    __shared__ float vs[MDIM];
    __shared__ float part[4][MDIM];
    const int tid = threadIdx.x;
    if (tid < MDIM) vs[tid] = vm[tid];
    __syncthreads();
    const int kg = tid >> 8;           // 0..3
    const int n  = tid & 255;
    float acc = 0.f;
    #pragma unroll 16
    for (int k0 = 0; k0 < 64; k0++) {
        int k = kg * 64 + k0;
        acc += vs[k] * W2[k * MDIM + n];
    }
    part[kg][n] = acc;
    __syncthreads();
    if (tid < MDIM)
        ap_cbias[tid] = part[0][tid] + part[1][tid] + part[2][tid] + part[3][tid];
}

// ---------------- kernel 2: fused scores + exp + weighted partial sum ----------------
__global__ void __launch_bounds__(256, 2)
ap_scores_kernel(const float* __restrict__ x, const float* __restrict__ vm) {
    extern __shared__ char dsm[];
    __shared__ float2 cbvm[MDIM];            // 2 KB
    __shared__ float  sred[4][TILE_M];       // 1 KB

    const int tid   = threadIdx.x;
    const int wid   = tid >> 5;
    const int lane  = tid & 31;
    const int g     = lane >> 2;        // groupID
    const int tig   = lane & 3;         // thread-in-group
    const int mhalf = wid >> 2;         // rows 0-31 / 32-63
    const int nquad = wid & 3;          // cols q*64..
    const int m0    = mhalf * 32;
    const int n0    = nquad * 64;

    uint32_t raw  = smem_u32(dsm);
    uint32_t base = (raw + 1023u) & ~1023u;
    const uint32_t aA = base;                   // 64 x 264 halves
    const uint32_t aB = base + A_BYTES;         // 2 x (256 x 72 halves)
    // epilogue scratch aliased into the (then-dead) B region:
    char* dsm_base = dsm + (base - raw);
    float*  se  = reinterpret_cast<float*>(dsm_base + A_BYTES);          // 64 floats
    float2* spw = reinterpret_cast<float2*>(dsm_base + A_BYTES + 512);   // [2][128]

    cbvm[tid] = make_float2(ap_cbias[tid], vm[tid]);

    const __half* wt = ap_Wt16;
    auto prefetchB = [&](int c) {
        uint32_t dstb = aB + (c & 1) * B_BYTES;
        #pragma unroll
        for (int it = 0; it < 8; it++) {
            int idx = it * 256 + tid;              // 0..2047
            int n = idx >> 3, jj = idx & 7;
            CP_ASYNC16(dstb + n * B_ROW_BYTES + jj * 16,
                       (const void*)(wt + n * MDIM + c * 64 + jj * 8));
        }
    };
    prefetchB(0);
    CP_COMMIT();

    // ---- pipelined A-chunk load: LDG into regs, later cvt+STS ----
    const float* xt = x + (size_t)blockIdx.x * TILE_M * MDIM;
    float4 stg[4];
    auto ldgA = [&](int c) {                       // 64 rows x 64 cols fp32
        #pragma unroll
        for (int it = 0; it < 4; it++) {
            int idx  = it * 256 + tid;             // 0..1023 float4s
            int row  = idx >> 4;
            int col0 = c * 64 + (idx & 15) * 4;
            stg[it] = *(const float4*)(xt + row * MDIM + col0);
        }
    };
    auto stsA = [&](int c) {
        #pragma unroll
        for (int it = 0; it < 4; it++) {
            int idx  = it * 256 + tid;
            int row  = idx >> 4;
            int col0 = c * 64 + (idx & 15) * 4;
            __half2 h0 = __floats2half2_rn(stg[it].x, stg[it].y);
            __half2 h1 = __floats2half2_rn(stg[it].z, stg[it].w);
            sts_u64(aA + row * A_ROW_BYTES + col0 * 2, *(uint32_t*)&h0, *(uint32_t*)&h1);
        }
    };

    // prologue: A chunk 0 only
    ldgA(0);
    stsA(0);

    // fragment row offsets
    uint32_t arow[2], brow[8];
    #pragma unroll
    for (int mi = 0; mi < 2; mi++) arow[mi] = (m0 + mi * 16 + g) * A_ROW_BYTES + tig * 4;
    #pragma unroll
    for (int ni = 0; ni < 8; ni++) brow[ni] = (n0 + ni * 8 + g) * B_ROW_BYTES + tig * 4;

    float acc[2][8][4];
    #pragma unroll
    for (int mi = 0; mi < 2; mi++)
        #pragma unroll
        for (int ni = 0; ni < 8; ni++)
            #pragma unroll
            for (int j = 0; j < 4; j++) acc[mi][ni][j] = 0.f;

    // ---- main loop: 4 K=64 chunks; B double-buffered, A chunk pipelined ----
    #pragma unroll
    for (int c = 0; c < 4; c++) {
        if (c < 3) {
            ldgA(c + 1);                            // issue x loads early (latency hidden by MMA)
            prefetchB(c + 1); CP_COMMIT(); CP_WAIT1();
        } else {
            CP_WAIT0();
        }
        __syncthreads();                            // B chunk c + A chunk c visible
        uint32_t abase = aA + c * 128;
        uint32_t bbase = aB + (c & 1) * B_BYTES;
        #pragma unroll
        for (int kk = 0; kk < 4; kk++) {
            uint32_t a[2][4];
            #pragma unroll
            for (int mi = 0; mi < 2; mi++) {
                uint32_t ad = abase + arow[mi] + kk * 32;
                a[mi][0] = lds_u32(ad);
                a[mi][1] = lds_u32(ad + 8 * A_ROW_BYTES);
                a[mi][2] = lds_u32(ad + 16);
                a[mi][3] = lds_u32(ad + 8 * A_ROW_BYTES + 16);
            }
            #pragma unroll
            for (int ni = 0; ni < 8; ni++) {
                uint32_t bd = bbase + brow[ni] + kk * 32;
                uint32_t b0 = lds_u32(bd);
                uint32_t b1 = lds_u32(bd + 16);
                #pragma unroll
                for (int mi = 0; mi < 2; mi++) mma16816(acc[mi][ni], a[mi], b0, b1);
            }
        }
        if (c < 3) stsA(c + 1);                     // write next A chunk (distinct region)
        __syncthreads();
    }

    // ---- epilogue A: score[r] = sum_col tanh(D + cb[col]) * vm[col] ----
    float rs[2][2];
    #pragma unroll
    for (int mi = 0; mi < 2; mi++) { rs[mi][0] = 0.f; rs[mi][1] = 0.f; }
    #pragma unroll
    for (int mi = 0; mi < 2; mi++)
        #pragma unroll
        for (int ni = 0; ni < 8; ni++)
            #pragma unroll
            for (int j = 0; j < 4; j++) {
                int col = n0 + ni * 8 + tig * 2 + (j & 1);
                float2 cv = cbvm[col];
                rs[mi][j >> 1] += tanh_fast(acc[mi][ni][j] + cv.x) * cv.y;
            }
    #pragma unroll
    for (int mi = 0; mi < 2; mi++)
        #pragma unroll
        for (int h = 0; h < 2; h++) {
            float v = rs[mi][h];
            v += __shfl_xor_sync(0xFFFFFFFFu, v, 1);
            v += __shfl_xor_sync(0xFFFFFFFFu, v, 2);
            if (tig == 0) sred[nquad][m0 + mi * 16 + h * 8 + g] = v;
        }
    __syncthreads();

    // ---- epilogue B: e = exp(score) ----
    if (tid < TILE_M) {
        float s = sred[0][tid] + sred[1][tid] + sred[2][tid] + sred[3][tid];
        se[tid] = __expf(s);
    }
    __syncthreads();

    // ---- epilogue C: partial[col] = sum_r e[r] * x_fp16[r][col] ----
    {
        const int c2 = tid & 127;       // half2 column pair
        const int rg = tid >> 7;        // row group 0/1
        float2 a2 = make_float2(0.f, 0.f);
        uint32_t ab = aA + rg * 32 * A_ROW_BYTES + c2 * 4;
        #pragma unroll 8
        for (int r = 0; r < 32; r++) {
            float e = se[rg * 32 + r];
            uint32_t p = lds_u32(ab + r * A_ROW_BYTES);
            float2 xv = __half22float2(*reinterpret_cast<__half2*>(&p));
            a2.x += e * xv.x;
            a2.y += e * xv.y;
        }
        spw[rg * 128 + c2] = a2;
    }
    __syncthreads();
    if (tid < 128) {
        float2 p0 = spw[tid], p1 = spw[128 + tid];
        float2 r = make_float2(p0.x + p1.x, p0.y + p1.y);
        *(float2*)(ap_partials + (size_t)blockIdx.x * MDIM + tid * 2) = r;
    }
    if (tid == 128) {
        float s = 0.f;
        #pragma unroll 8
        for (int r = 0; r < TILE_M; r++) s += se[r];
        ap_sume[blockIdx.x] = s;
    }
}

// ---------------- kernel 3: final reduce -> out (16,1,256) ----------------
// grid (BATCH, 8): block handles 32 cols; 8 row-groups x 16 tiles each.
__global__ void __launch_bounds__(256) ap_final2_kernel(float* __restrict__ out) {
    __shared__ float sp[8][32];
    __shared__ float swsum[8];
    const int b   = blockIdx.x;
    const int cg  = blockIdx.y;
    const int tid = threadIdx.x;
    const int col = cg * 32 + (tid & 31);
    const int rg  = tid >> 5;            // 0..7

    const float* pp = ap_partials + (size_t)b * TILES_PER_B * MDIM + col;
    float acc = 0.f;
    #pragma unroll
    for (int i = 0; i < 16; i++)
        acc += pp[(size_t)(rg * 16 + i) * MDIM];
    sp[rg][tid & 31] = acc;

    // sumE over 128 tiles: 8 warps x 16 values each
    {
        const int w = tid >> 5, l = tid & 31;
        float s = (l < 16) ? ap_sume[b * TILES_PER_B + w * 16 + l] : 0.f;
        #pragma unroll
        for (int o = 8; o > 0; o >>= 1) s += __shfl_xor_sync(0xFFFFFFFFu, s, o);
        if (l == 0) swsum[w] = s;
    }
    __syncthreads();
    if (tid < 32) {
        float r = 0.f, ssum = 0.f;
        #pragma unroll
        for (int q = 0; q < 8; q++) { r += sp[q][tid]; ssum += swsum[q]; }
        out[b * MDIM + col] = r / ssum;
    }
}

// ---------------- launch ----------------
extern "C" void kernel_launch(void* const* d_in, const int* in_sizes, int n_in,
                              void* d_out, int out_size) {
    const float* x  = (const float*)d_in[0];
    const float* W1 = (const float*)d_in[1];
    const float* W2 = (const float*)d_in[2];
    const float* vm = (const float*)d_in[3];
    float* out = (float*)d_out;

    cudaFuncSetAttribute(ap_scores_kernel, cudaFuncAttributeMaxDynamicSharedMemorySize, DYN_SMEM);

    ap_prep_w_kernel<<<32, 256>>>(W1);
    ap_prep_cbias_kernel<<<1, 1024>>>(W2, vm);
    ap_scores_kernel<<<N_TILES, 256, DYN_SMEM>>>(x, vm);
    ap_final2_kernel<<<dim3(BATCH, 8), 256>>>(out);
}

// round 11
// speedup vs baseline: 1.1145x; 1.1145x over previous
#include <cuda_runtime.h>
#include <cuda_fp16.h>
#include <cstdint>

#define BATCH      16
#define TSEQ       8192
#define MDIM       256
#define ROWS_TOTAL (BATCH * TSEQ)          // 131072
#define TILE_M     64
#define N_TILES    (ROWS_TOTAL / TILE_M)   // 2048
#define TILES_PER_B (TSEQ / TILE_M)        // 128
#define A_ROW_BYTES 528                    // 264 halves (256 + 8 pad)
#define A_BYTES    (TILE_M * A_ROW_BYTES)  // 33792
#define B_ROW_BYTES 144                    // 72 halves (64 + 8 pad)
#define B_BYTES    (MDIM * B_ROW_BYTES)    // 36864
#define DYN_SMEM   (1024 + A_BYTES + 2 * B_BYTES)   // 108544 (x2 CTA = 217KB/SM)

// ---------------- helpers ----------------
__device__ __forceinline__ uint32_t smem_u32(const void* p) {
    uint32_t a;
    asm("{ .reg .u64 t; cvta.to.shared.u64 t, %1; cvt.u32.u64 %0, t; }" : "=r"(a) : "l"(p));
    return a;
}
#define CP_ASYNC16(dst, src) \
    asm volatile("cp.async.cg.shared.global [%0], [%1], 16;" :: "r"(dst), "l"(src) : "memory")
#define CP_COMMIT() asm volatile("cp.async.commit_group;" ::: "memory")
#define CP_WAIT1()  asm volatile("cp.async.wait_group 1;" ::: "memory")
#define CP_WAIT0()  asm volatile("cp.async.wait_group 0;" ::: "memory")

__device__ __forceinline__ uint32_t lds_u32(uint32_t a) {
    uint32_t v;
    asm volatile("ld.shared.u32 %0, [%1];" : "=r"(v) : "r"(a));
    return v;
}
__device__ __forceinline__ void sts_u128(uint32_t a, uint32_t v0, uint32_t v1, uint32_t v2, uint32_t v3) {
    asm volatile("st.shared.v4.u32 [%0], {%1, %2, %3, %4};"
                 :: "r"(a), "r"(v0), "r"(v1), "r"(v2), "r"(v3) : "memory");
}
__device__ __forceinline__ void mma16816(float* c, const uint32_t* a, uint32_t b0, uint32_t b1) {
    asm volatile(
        "mma.sync.aligned.m16n8k16.row.col.f32.f16.f16.f32 "
        "{%0,%1,%2,%3}, {%4,%5,%6,%7}, {%8,%9}, {%0,%1,%2,%3};"
        : "+f"(c[0]), "+f"(c[1]), "+f"(c[2]), "+f"(c[3])
        : "r"(a[0]), "r"(a[1]), "r"(a[2]), "r"(a[3]), "r"(b0), "r"(b1));
}
__device__ __forceinline__ float tanh_fast(float x) {
    float y;
    asm("tanh.approx.f32 %0, %1;" : "=f"(y) : "f"(x));
    return y;
}

// ---------------- global scratch ----------------
__device__ float  ap_cbias[MDIM];                 // vm @ W2
__device__ __half ap_Wt16[MDIM * MDIM];           // [n][k] = fp16(W1^T)
__device__ float  ap_partials[N_TILES * MDIM];    // per-CTA  sum_t e_t * x[t][col]
__device__ float  ap_sume[N_TILES];               // per-CTA  sum_t e_t

// ---------------- kernel 1: fused prep (blocks 0-7: W1^T->fp16, block 8: cbias) ----------------
__global__ void __launch_bounds__(1024) ap_prep_kernel(const float* __restrict__ W1,
                                                       const float* __restrict__ W2,
                                                       const float* __restrict__ vm) {
    const int tid = threadIdx.x;
    if (blockIdx.x < 8) {
        // W conversion: block b handles k-rows [b*32, b*32+32); thread: n = tid&255, 8 k's
        const int n  = tid & 255;
        const int k0 = blockIdx.x * 32 + (tid >> 8) * 8;
        __half h[8];
        #pragma unroll
        for (int j = 0; j < 8; j++)
            h[j] = __float2half_rn(W1[(k0 + j) * MDIM + n]);   // W1[k][n]
        *reinterpret_cast<uint4*>(ap_Wt16 + n * MDIM + k0) = *reinterpret_cast<uint4*>(h);
    } else {
        // cbias = vm @ W2 (4-way k split)
        __shared__ float vs[MDIM];
        __shared__ float part[4][MDIM];
        if (tid < MDIM) vs[tid] = vm[tid];
        __syncthreads();
        const int kg = tid >> 8;           // 0..3
        const int n  = tid & 255;
        float acc = 0.f;
        #pragma unroll 16
        for (int k0 = 0; k0 < 64; k0++) {
            int k = kg * 64 + k0;
            acc += vs[k] * W2[k * MDIM + n];
        }
        part[kg][n] = acc;
        __syncthreads();
        if (tid < MDIM)
            ap_cbias[tid] = part[0][tid] + part[1][tid] + part[2][tid] + part[3][tid];
    }
}

// ---------------- kernel 2: fused scores + exp + weighted partial sum ----------------
__global__ void __launch_bounds__(256, 2)
ap_scores_kernel(const float* __restrict__ x, const float* __restrict__ vm) {
    extern __shared__ char dsm[];
    __shared__ float2 cbvm[MDIM];            // 2 KB
    __shared__ float  sred[4][TILE_M];       // 1 KB

    const int tid   = threadIdx.x;
    const int wid   = tid >> 5;
    const int lane  = tid & 31;
    const int g     = lane >> 2;        // groupID
    const int tig   = lane & 3;         // thread-in-group
    const int mhalf = wid >> 2;         // rows 0-31 / 32-63
    const int nquad = wid & 3;          // cols q*64..
    const int m0    = mhalf * 32;
    const int n0    = nquad * 64;

    uint32_t raw  = smem_u32(dsm);
    uint32_t base = (raw + 1023u) & ~1023u;
    const uint32_t aA = base;                   // 64 x 264 halves
    const uint32_t aB = base + A_BYTES;         // 2 x (256 x 72 halves)
    // epilogue scratch aliased into the (then-dead) B region:
    char* dsm_base = dsm + (base - raw);
    float*  se  = reinterpret_cast<float*>(dsm_base + A_BYTES);          // 64 floats
    float2* spw = reinterpret_cast<float2*>(dsm_base + A_BYTES + 512);   // [2][128]

    cbvm[tid] = make_float2(ap_cbias[tid], vm[tid]);

    const __half* wt = ap_Wt16;
    auto prefetchB = [&](int c) {
        uint32_t dstb = aB + (c & 1) * B_BYTES;
        #pragma unroll
        for (int it = 0; it < 8; it++) {
            int idx = it * 256 + tid;              // 0..2047
            int n = idx >> 3, jj = idx & 7;
            CP_ASYNC16(dstb + n * B_ROW_BYTES + jj * 16,
                       (const void*)(wt + n * MDIM + c * 64 + jj * 8));
        }
    };
    prefetchB(0);
    CP_COMMIT();

    // ---- load x tile (64 x 256 fp32) -> fp16 in smem ----
    const float* xt = x + (size_t)blockIdx.x * TILE_M * MDIM;
    #pragma unroll
    for (int it = 0; it < 8; it++) {
        int id   = it * 256 + tid;      // 0..2047 groups of 8 floats
        int row  = id >> 5;
        int col0 = (id & 31) * 8;
        float4 v0 = *(const float4*)(xt + row * MDIM + col0);
        float4 v1 = *(const float4*)(xt + row * MDIM + col0 + 4);
        __half2 h0 = __floats2half2_rn(v0.x, v0.y);
        __half2 h1 = __floats2half2_rn(v0.z, v0.w);
        __half2 h2 = __floats2half2_rn(v1.x, v1.y);
        __half2 h3 = __floats2half2_rn(v1.z, v1.w);
        sts_u128(aA + row * A_ROW_BYTES + col0 * 2,
                 *(uint32_t*)&h0, *(uint32_t*)&h1, *(uint32_t*)&h2, *(uint32_t*)&h3);
    }

    // fragment row offsets
    uint32_t arow[2], brow[8];
    #pragma unroll
    for (int mi = 0; mi < 2; mi++) arow[mi] = (m0 + mi * 16 + g) * A_ROW_BYTES + tig * 4;
    #pragma unroll
    for (int ni = 0; ni < 8; ni++) brow[ni] = (n0 + ni * 8 + g) * B_ROW_BYTES + tig * 4;

    float acc[2][8][4];
    #pragma unroll
    for (int mi = 0; mi < 2; mi++)
        #pragma unroll
        for (int ni = 0; ni < 8; ni++)
            #pragma unroll
            for (int j = 0; j < 4; j++) acc[mi][ni][j] = 0.f;

    // ---- main loop: 4 K=64 chunks, double-buffered B ----
    #pragma unroll
    for (int c = 0; c < 4; c++) {
        if (c < 3) { prefetchB(c + 1); CP_COMMIT(); CP_WAIT1(); }
        else       { CP_WAIT0(); }
        __syncthreads();
        uint32_t abase = aA + c * 128;
        uint32_t bbase = aB + (c & 1) * B_BYTES;
        #pragma unroll
        for (int kk = 0; kk < 4; kk++) {
            uint32_t a[2][4];
            #pragma unroll
            for (int mi = 0; mi < 2; mi++) {
                uint32_t ad = abase + arow[mi] + kk * 32;
                a[mi][0] = lds_u32(ad);
                a[mi][1] = lds_u32(ad + 8 * A_ROW_BYTES);
                a[mi][2] = lds_u32(ad + 16);
                a[mi][3] = lds_u32(ad + 8 * A_ROW_BYTES + 16);
            }
            #pragma unroll
            for (int ni = 0; ni < 8; ni++) {
                uint32_t bd = bbase + brow[ni] + kk * 32;
                uint32_t b0 = lds_u32(bd);
                uint32_t b1 = lds_u32(bd + 16);
                #pragma unroll
                for (int mi = 0; mi < 2; mi++) mma16816(acc[mi][ni], a[mi], b0, b1);
            }
        }
        __syncthreads();
    }

    // ---- epilogue A: score[r] = sum_col tanh(D + cb[col]) * vm[col] ----
    float rs[2][2];
    #pragma unroll
    for (int mi = 0; mi < 2; mi++) { rs[mi][0] = 0.f; rs[mi][1] = 0.f; }
    #pragma unroll
    for (int mi = 0; mi < 2; mi++)
        #pragma unroll
        for (int ni = 0; ni < 8; ni++)
            #pragma unroll
            for (int j = 0; j < 4; j++) {
                int col = n0 + ni * 8 + tig * 2 + (j & 1);
                float2 cv = cbvm[col];
                rs[mi][j >> 1] += tanh_fast(acc[mi][ni][j] + cv.x) * cv.y;
            }
    #pragma unroll
    for (int mi = 0; mi < 2; mi++)
        #pragma unroll
        for (int h = 0; h < 2; h++) {
            float v = rs[mi][h];
            v += __shfl_xor_sync(0xFFFFFFFFu, v, 1);
            v += __shfl_xor_sync(0xFFFFFFFFu, v, 2);
            if (tig == 0) sred[nquad][m0 + mi * 16 + h * 8 + g] = v;
        }
    __syncthreads();

    // ---- epilogue B: e = exp(score) (scores bounded; no max needed) ----
    if (tid < TILE_M) {
        float s = sred[0][tid] + sred[1][tid] + sred[2][tid] + sred[3][tid];
        se[tid] = __expf(s);
    }
    __syncthreads();

    // ---- epilogue C: partial[col] = sum_r e[r] * x_fp16[r][col] ----
    {
        const int c2 = tid & 127;       // half2 column pair
        const int rg = tid >> 7;        // row group 0/1
        float2 a2 = make_float2(0.f, 0.f);
        uint32_t ab = aA + rg * 32 * A_ROW_BYTES + c2 * 4;
        #pragma unroll 8
        for (int r = 0; r < 32; r++) {
            float e = se[rg * 32 + r];
            uint32_t p = lds_u32(ab + r * A_ROW_BYTES);
            float2 xv = __half22float2(*reinterpret_cast<__half2*>(&p));
            a2.x += e * xv.x;
            a2.y += e * xv.y;
        }
        spw[rg * 128 + c2] = a2;
    }
    // warp 4 (tids 128-159) computes sumE in parallel with the spw writes above
    if (wid == 4) {
        float s = se[lane] + se[lane + 32];
        #pragma unroll
        for (int o = 16; o > 0; o >>= 1) s += __shfl_xor_sync(0xFFFFFFFFu, s, o);
        if (lane == 0) ap_sume[blockIdx.x] = s;
    }
    __syncthreads();
    if (tid < 128) {
        float2 p0 = spw[tid], p1 = spw[128 + tid];
        float2 r = make_float2(p0.x + p1.x, p0.y + p1.y);
        *(float2*)(ap_partials + (size_t)blockIdx.x * MDIM + tid * 2) = r;
    }
}

// ---------------- kernel 3: final reduce -> out (16,1,256) ----------------
// grid (BATCH, 8): block handles 32 cols; 8 row-groups x 16 tiles each.
__global__ void __launch_bounds__(256) ap_final2_kernel(float* __restrict__ out) {
    __shared__ float sp[8][32];
    __shared__ float swsum[8];
    const int b   = blockIdx.x;
    const int cg  = blockIdx.y;
    const int tid = threadIdx.x;
    const int col = cg * 32 + (tid & 31);
    const int rg  = tid >> 5;            // 0..7

    const float* pp = ap_partials + (size_t)b * TILES_PER_B * MDIM + col;
    float acc = 0.f;
    #pragma unroll
    for (int i = 0; i < 16; i++)
        acc += pp[(size_t)(rg * 16 + i) * MDIM];
    sp[rg][tid & 31] = acc;

    // sumE over 128 tiles: 8 warps x 16 values each
    {
        const int w = tid >> 5, l = tid & 31;
        float s = (l < 16) ? ap_sume[b * TILES_PER_B + w * 16 + l] : 0.f;
        #pragma unroll
        for (int o = 8; o > 0; o >>= 1) s += __shfl_xor_sync(0xFFFFFFFFu, s, o);
        if (l == 0) swsum[w] = s;
    }
    __syncthreads();
    if (tid < 32) {
        float r = 0.f, ssum = 0.f;
        #pragma unroll
        for (int q = 0; q < 8; q++) { r += sp[q][tid]; ssum += swsum[q]; }
        out[b * MDIM + col] = r / ssum;
    }
}

// ---------------- launch ----------------
extern "C" void kernel_launch(void* const* d_in, const int* in_sizes, int n_in,
                              void* d_out, int out_size) {
    const float* x  = (const float*)d_in[0];
    const float* W1 = (const float*)d_in[1];
    const float* W2 = (const float*)d_in[2];
    const float* vm = (const float*)d_in[3];
    float* out = (float*)d_out;

    cudaFuncSetAttribute(ap_scores_kernel, cudaFuncAttributeMaxDynamicSharedMemorySize, DYN_SMEM);

    ap_prep_kernel<<<9, 1024>>>(W1, W2, vm);
    ap_scores_kernel<<<N_TILES, 256, DYN_SMEM>>>(x, vm);
    ap_final2_kernel<<<dim3(BATCH, 8), 256>>>(out);
}